// round 12
// baseline (speedup 1.0000x reference)
#include <cuda_runtime.h>
#include <cuda_fp16.h>
#include <math.h>
#include <stdint.h>

#define B_  64
#define S_  2048
#define H_  512
#define M_  (B_ * S_)

// ---------------- device scratch (no allocs allowed) ----------------
__device__ __half g_Bf[H_ * H_];           // Wh^T fp16 [n][k]
__device__ float g_comb[B_ * H_];          // dec@Ws + bs + bh + bc
__device__ float g_epart[4 * M_];          // per-nc partial e sums

// ---------------- helpers ----------------
__device__ __forceinline__ uint32_t smem_u32(const void* p) {
    uint32_t a;
    asm("{ .reg .u64 t; cvta.to.shared.u64 t, %1; cvt.u32.u64 %0, t; }" : "=r"(a) : "l"(p));
    return a;
}
// accurate tanh: 2 MUFU, rel err ~1e-7, saturates correctly
__device__ __forceinline__ float tanh_acc(float x) {
    float e = __expf(2.0f * x);
    return 1.0f - __fdividef(2.0f, e + 1.0f);
}
__device__ __forceinline__ void ldsm4(uint32_t* r, uint32_t addr) {
    asm volatile("ldmatrix.sync.aligned.m8n8.x4.shared.b16 {%0,%1,%2,%3}, [%4];"
                 : "=r"(r[0]), "=r"(r[1]), "=r"(r[2]), "=r"(r[3]) : "r"(addr));
}
__device__ __forceinline__ void mma_f16(float* c, const uint32_t* a, uint32_t b0, uint32_t b1) {
    asm volatile(
        "mma.sync.aligned.m16n8k16.row.col.f32.f16.f16.f32 "
        "{%0,%1,%2,%3},{%4,%5,%6,%7},{%8,%9},{%0,%1,%2,%3};"
        : "+f"(c[0]), "+f"(c[1]), "+f"(c[2]), "+f"(c[3])
        : "r"(a[0]), "r"(a[1]), "r"(a[2]), "r"(a[3]), "r"(b0), "r"(b1));
}
__device__ __forceinline__ void cp16(uint32_t dst, const void* src) {
    asm volatile("cp.async.cg.shared.global [%0], [%1], 16;" :: "r"(dst), "l"(src));
}
__device__ __forceinline__ void lds128f(float4& v, uint32_t addr) {
    asm volatile("ld.shared.v4.f32 {%0,%1,%2,%3}, [%4];"
                 : "=f"(v.x), "=f"(v.y), "=f"(v.z), "=f"(v.w) : "r"(addr));
}
__device__ __forceinline__ void sts64(uint32_t addr, uint32_t a, uint32_t b) {
    asm volatile("st.shared.v2.b32 [%0], {%1,%2};" :: "r"(addr), "r"(a), "r"(b));
}
__device__ __forceinline__ uint32_t h2u(__half2 h) { return *(uint32_t*)&h; }

// ---------------------------------------------------------------------------
// Pack B: Wh [k][n] fp32 -> g_Bf [n][k] fp16 (transpose)
// ---------------------------------------------------------------------------
__global__ void bpack_kernel(const float* __restrict__ Wh)
{
    const int n  = blockIdx.x;              // 0..511
    const int k4 = threadIdx.x * 4;         // 128 threads x 4 k
    __half2 lo = __floats2half2_rn(Wh[(size_t)(k4 + 0) * H_ + n], Wh[(size_t)(k4 + 1) * H_ + n]);
    __half2 hi = __floats2half2_rn(Wh[(size_t)(k4 + 2) * H_ + n], Wh[(size_t)(k4 + 3) * H_ + n]);
    *(uint2*)(g_Bf + (size_t)n * H_ + k4) = make_uint2(h2u(lo), h2u(hi));
}

// ---------------------------------------------------------------------------
// comb[b][n] = dec[b] @ Ws[:,n] + bs + bh + bc
// ---------------------------------------------------------------------------
__global__ void dec_comb_kernel(const float* __restrict__ dec,
                                const float* __restrict__ Ws,
                                const float* __restrict__ bs,
                                const float* __restrict__ bh,
                                const float* __restrict__ bc)
{
    const int b  = blockIdx.x;
    const int nh = blockIdx.y;
    const int tid = threadIdx.x;
    __shared__ float dh[H_];
    __shared__ float red[4][64];

    dh[tid]       = dec[b * H_ + tid];
    dh[tid + 256] = dec[b * H_ + tid + 256];
    __syncthreads();

    const int nl = tid & 63;
    const int n  = nh * 64 + nl;
    const int ks = tid >> 6;
    float acc = 0.f;
    #pragma unroll 8
    for (int h = ks * 128; h < ks * 128 + 128; ++h)
        acc = fmaf(dh[h], Ws[(size_t)h * H_ + n], acc);
    red[ks][nl] = acc;
    __syncthreads();
    if (ks == 0) {
        float s = red[0][nl] + red[1][nl] + red[2][nl] + red[3][nl];
        g_comb[b * H_ + n] = s + bs[n] + bh[n] + bc[n];
    }
}

// ---------------------------------------------------------------------------
// Main: 128x128x512 fp16 HMMA GEMM with IN-KERNEL fp32->fp16 A conversion
// grid (4 nc, 1024 m), 256 threads = 8 warps (warpM 0..1 x warpN 0..3),
// warp tile 64x32; 16 k-chunks of 32; rings: fp32 staging x2, fp16 A x2
// (pitch 80), B x3 (pitch 80); one cp.async group + one barrier per iter.
// ---------------------------------------------------------------------------
#define STG_STAGE 16384                   // 128 rows x 128B fp32
#define A16_STAGE 10240                   // 128 rows x 80B (64B data)
#define B16_STAGE 10240
#define OFF_STG   0                       // 2 stages
#define OFF_A16   32768                   // 2 stages
#define OFF_B16   53248                   // 3 stages
#define OFF_COMB  83968
#define OFF_WC    84480
#define OFF_VW    84992
#define OFF_ERED  0                       // overlays staging after k-loop
#define SMEM_DYN  85504

__global__ __launch_bounds__(256, 2)
void attn_hmma_kernel(const float* __restrict__ enc,
                      const float* __restrict__ cov,
                      const float* __restrict__ Wc,
                      const float* __restrict__ v_w)
{
    extern __shared__ char sm[];
    const uint32_t sbase = smem_u32(sm);
    const int tid  = threadIdx.x;
    const int wid  = tid >> 5;
    const int lane = tid & 31;
    const int nc     = blockIdx.x;          // 0..3 (fast-varying: A fp32 L2 reuse)
    const int mBase  = blockIdx.y * 128;
    const int ncBase = nc * 128;
    const int b      = mBase >> 11;

    // epilogue constants (ordered before use by the loop barriers)
    if (tid < 128) {
        ((float*)(sm + OFF_COMB))[tid] = g_comb[b * H_ + ncBase + tid];
        ((float*)(sm + OFF_WC))[tid]   = Wc[ncBase + tid];
        ((float*)(sm + OFF_VW))[tid]   = v_w[ncBase + tid];
    }

    // cp.async mappings (per chunk):
    // A fp32 staging: 1024 x16B /256thr = 4 per thread
    const char* aSrc[4]; uint32_t aDst[4];
    #pragma unroll
    for (int p = 0; p < 4; ++p) {
        const int idx = p * 256 + tid;
        const int r = idx >> 3, cc = idx & 7;
        aSrc[p] = (const char*)enc + (size_t)(mBase + r) * 2048 + cc * 16;
        aDst[p] = sbase + OFF_STG + r * 128 + cc * 16;
    }
    // B fp16: 512 x16B /256thr = 2 per thread (pitch-80 dst)
    const char* bSrc[2]; uint32_t bDst[2];
    #pragma unroll
    for (int p = 0; p < 2; ++p) {
        const int idx = p * 256 + tid;
        const int r = idx >> 2, cc = idx & 3;
        bSrc[p] = (const char*)g_Bf + (size_t)(ncBase + r) * 1024 + cc * 16;
        bDst[p] = sbase + OFF_B16 + r * 80 + cc * 16;
    }

#define CP_CHUNK(kc) do { \
    const uint32_t _sOff = (uint32_t)(((kc) & 1) * STG_STAGE); \
    const uint32_t _bOff = (uint32_t)(((kc) % 3) * B16_STAGE); \
    const int _ka = (kc) * 128, _kb = (kc) * 64; \
    _Pragma("unroll") \
    for (int _p = 0; _p < 4; ++_p) cp16(aDst[_p] + _sOff, aSrc[_p] + _ka); \
    _Pragma("unroll") \
    for (int _p = 0; _p < 2; ++_p) cp16(bDst[_p] + _bOff, bSrc[_p] + _kb); \
    asm volatile("cp.async.commit_group;" ::: "memory"); \
} while (0)

// convert staged fp32 chunk kc -> fp16 ring (same parity slot)
#define CONVERT(kc) do { \
    const uint32_t _in  = sbase + OFF_STG + ((kc) & 1) * STG_STAGE; \
    const uint32_t _out = sbase + OFF_A16 + ((kc) & 1) * A16_STAGE; \
    _Pragma("unroll") \
    for (int _p = 0; _p < 4; ++_p) { \
        const int _idx = _p * 256 + tid; \
        float4 _v; lds128f(_v, _in + _idx * 16); \
        const int _r = _idx >> 3, _cc = _idx & 7; \
        sts64(_out + _r * 80 + _cc * 8, \
              h2u(__floats2half2_rn(_v.x, _v.y)), h2u(__floats2half2_rn(_v.z, _v.w))); \
    } \
} while (0)

    const int warpM = wid >> 2;            // 0..1 -> 64 rows
    const int warpN = wid & 3;             // 0..3 -> 32 cols

    // ldsm offsets within a pitch-80 matrix; s in {0,1} adds 32B
    uint32_t offA[4][2], offB[2][2];
    {
        const int rowA = warpM * 64 + (lane & 7) + ((lane >> 3) & 1) * 8;
        const int cA   = (lane >> 4);                   // 0..1
        #pragma unroll
        for (int mI = 0; mI < 4; ++mI)
            #pragma unroll
            for (int s = 0; s < 2; ++s)
                offA[mI][s] = (uint32_t)((rowA + mI * 16) * 80 + (s * 2 + cA) * 16);
        const int rowB = warpN * 32 + (lane & 7) + ((lane & 16) ? 8 : 0);
        const int cB   = (lane >> 3) & 1;
        #pragma unroll
        for (int p = 0; p < 2; ++p)
            #pragma unroll
            for (int s = 0; s < 2; ++s)
                offB[p][s] = (uint32_t)((rowB + p * 16) * 80 + (s * 2 + cB) * 16);
    }

    float acc[4][4][4];
    #pragma unroll
    for (int i = 0; i < 4; ++i)
        #pragma unroll
        for (int j = 0; j < 4; ++j)
            #pragma unroll
            for (int q = 0; q < 4; ++q) acc[i][j][q] = 0.f;

    // prologue: stage chunks 0,1; convert chunk 0
    CP_CHUNK(0);
    CP_CHUNK(1);
    asm volatile("cp.async.wait_group 1;" ::: "memory");   // G0 done
    __syncthreads();
    CONVERT(0);

    #pragma unroll 1
    for (int c = 0; c < 16; ++c) {
        // all committed groups done: staging/B through chunk c+1 resident
        asm volatile("cp.async.wait_group 0;" ::: "memory");
        __syncthreads();   // publishes CONVERT(c) from prev iter; guards rings

        if (c + 2 < 16) CP_CHUNK(c + 2);       // overlaps with convert + MMA
        if (c + 1 < 16) CONVERT(c + 1);

        const uint32_t ab = sbase + OFF_A16 + (c & 1) * A16_STAGE;
        const uint32_t bb = sbase + OFF_B16 + (c % 3) * B16_STAGE;
        #pragma unroll
        for (int s = 0; s < 2; ++s) {          // each s = 16 k
            uint32_t Af[4][4], Bf[2][4];
            #pragma unroll
            for (int p = 0; p < 2; ++p)    ldsm4(Bf[p], bb + offB[p][s]);
            #pragma unroll
            for (int mI = 0; mI < 4; ++mI) ldsm4(Af[mI], ab + offA[mI][s]);
            #pragma unroll
            for (int mI = 0; mI < 4; ++mI)
                #pragma unroll
                for (int nI = 0; nI < 4; ++nI)
                    mma_f16(acc[mI][nI], Af[mI], Bf[nI >> 1][(nI & 1) * 2], Bf[nI >> 1][(nI & 1) * 2 + 1]);
        }
    }

    // ---- fused epilogue: tanh + v-dot, reduce across 16 column-threads ----
    const float* sComb = (const float*)(sm + OFF_COMB);
    const float* sWc   = (const float*)(sm + OFF_WC);
    const float* sVw   = (const float*)(sm + OFF_VW);
    float* ered = (float*)(sm + OFF_ERED);     // overlays staging (k-loop done)
    const int col = warpN * 4 + (lane & 3);
    __syncthreads();                           // all warps past k-loop

    #pragma unroll
    for (int mI = 0; mI < 4; ++mI) {
        const int mlo = warpM * 64 + mI * 16 + (lane >> 2);
        const float covlo = cov[mBase + mlo];
        const float covhi = cov[mBase + mlo + 8];
        float elo = 0.f, ehi = 0.f;
        #pragma unroll
        for (int nI = 0; nI < 4; ++nI) {
            #pragma unroll
            for (int t = 0; t < 2; ++t) {
                const int n = warpN * 32 + nI * 8 + (lane & 3) * 2 + t;
                const float cb = sComb[n], wc = sWc[n], vw = sVw[n];
                elo = fmaf(vw, tanh_acc(acc[mI][nI][t]     + cb + covlo * wc), elo);
                ehi = fmaf(vw, tanh_acc(acc[mI][nI][t + 2] + cb + covhi * wc), ehi);
            }
        }
        ered[mlo * 16 + col]       = elo;
        ered[(mlo + 8) * 16 + col] = ehi;
    }
    __syncthreads();
    if (tid < 128) {
        float s = 0.f;
        #pragma unroll
        for (int t = 0; t < 16; ++t) s += ered[tid * 16 + t];
        g_epart[nc * M_ + mBase + tid] = s;
    }
#undef CP_CHUNK
#undef CONVERT
}

// ---------------------------------------------------------------------------
// Softmax over S=2048 per batch + coverage update (v_b shift-invariant)
// ---------------------------------------------------------------------------
__global__ __launch_bounds__(256)
void softmax_kernel(const float* __restrict__ cov, float* __restrict__ out)
{
    const int b   = blockIdx.x;
    const int tid = threadIdx.x;
    __shared__ float red[256];

    float local[8];
    float mx = -INFINITY;
    #pragma unroll
    for (int i = 0; i < 8; ++i) {
        const int idx = b * S_ + tid + i * 256;
        local[i] = g_epart[idx] + g_epart[M_ + idx] + g_epart[2 * M_ + idx] + g_epart[3 * M_ + idx];
        mx = fmaxf(mx, local[i]);
    }
    red[tid] = mx;
    __syncthreads();
    for (int s = 128; s > 0; s >>= 1) {
        if (tid < s) red[tid] = fmaxf(red[tid], red[tid + s]);
        __syncthreads();
    }
    const float m = red[0];
    __syncthreads();

    float sum = 0.f;
    #pragma unroll
    for (int i = 0; i < 8; ++i) {
        local[i] = __expf(local[i] - m);
        sum += local[i];
    }
    red[tid] = sum;
    __syncthreads();
    for (int s = 128; s > 0; s >>= 1) {
        if (tid < s) red[tid] += red[tid + s];
        __syncthreads();
    }
    const float inv = 1.0f / red[0];

    #pragma unroll
    for (int i = 0; i < 8; ++i) {
        const int idx = b * S_ + tid + i * 256;
        const float a = local[i] * inv;
        out[idx]      = a;
        out[M_ + idx] = cov[idx] + a;
    }
}

// ---------------------------------------------------------------------------
extern "C" void kernel_launch(void* const* d_in, const int* in_sizes, int n_in,
                              void* d_out, int out_size)
{
    const float* enc = (const float*)d_in[0];
    const float* dec = (const float*)d_in[1];
    const float* cov = (const float*)d_in[2];
    const float* Wh  = (const float*)d_in[3];
    const float* bh  = (const float*)d_in[4];
    const float* Ws  = (const float*)d_in[5];
    const float* bs  = (const float*)d_in[6];
    const float* Wc  = (const float*)d_in[7];
    const float* bc  = (const float*)d_in[8];
    const float* v_w = (const float*)d_in[9];
    float* out = (float*)d_out;

    cudaFuncSetAttribute(attn_hmma_kernel,
                         cudaFuncAttributeMaxDynamicSharedMemorySize, SMEM_DYN);

    bpack_kernel<<<H_, 128>>>(Wh);
    dec_comb_kernel<<<dim3(B_, 8), 256>>>(dec, Ws, bs, bh, bc);
    attn_hmma_kernel<<<dim3(4, M_ / 128), 256, SMEM_DYN>>>(enc, cov, Wc, v_w);
    softmax_kernel<<<B_, 256>>>(cov, out);
}

// round 13
// speedup vs baseline: 1.1109x; 1.1109x over previous
#include <cuda_runtime.h>
#include <cuda_fp16.h>
#include <math.h>
#include <stdint.h>

#define B_  64
#define S_  2048
#define H_  512
#define M_  (B_ * S_)

// ---------------- device scratch (no allocs allowed) ----------------
__device__ __half g_Af[(size_t)M_ * H_];   // 128 MB enc fp16
__device__ __half g_Bf[H_ * H_];           // Wh^T fp16 [n][k]
__device__ float g_comb[B_ * H_];          // dec@Ws + bs + bh + bc
__device__ float g_epart[4 * M_];          // per-nc partial e sums

// ---------------- helpers ----------------
__device__ __forceinline__ uint32_t smem_u32(const void* p) {
    uint32_t a;
    asm("{ .reg .u64 t; cvta.to.shared.u64 t, %1; cvt.u32.u64 %0, t; }" : "=r"(a) : "l"(p));
    return a;
}
// accurate tanh: 2 MUFU, rel err ~1e-7, saturates correctly
__device__ __forceinline__ float tanh_acc(float x) {
    float e = __expf(2.0f * x);
    return 1.0f - __fdividef(2.0f, e + 1.0f);
}
__device__ __forceinline__ void ldsm4(uint32_t* r, uint32_t addr) {
    asm volatile("ldmatrix.sync.aligned.m8n8.x4.shared.b16 {%0,%1,%2,%3}, [%4];"
                 : "=r"(r[0]), "=r"(r[1]), "=r"(r[2]), "=r"(r[3]) : "r"(addr));
}
__device__ __forceinline__ void mma_f16(float* c, const uint32_t* a, uint32_t b0, uint32_t b1) {
    asm volatile(
        "mma.sync.aligned.m16n8k16.row.col.f32.f16.f16.f32 "
        "{%0,%1,%2,%3},{%4,%5,%6,%7},{%8,%9},{%0,%1,%2,%3};"
        : "+f"(c[0]), "+f"(c[1]), "+f"(c[2]), "+f"(c[3])
        : "r"(a[0]), "r"(a[1]), "r"(a[2]), "r"(a[3]), "r"(b0), "r"(b1));
}
__device__ __forceinline__ void cp16(uint32_t dst, const void* src) {
    asm volatile("cp.async.cg.shared.global [%0], [%1], 16;" :: "r"(dst), "l"(src));
}
__device__ __forceinline__ uint32_t h2u(__half2 h) { return *(uint32_t*)&h; }

// ---------------------------------------------------------------------------
// Pack A: enc fp32 -> g_Af fp16 (512 thr x 2 float4 per thread)
// ---------------------------------------------------------------------------
__global__ void apack_kernel(const float* __restrict__ A)
{
    const size_t base = (size_t)blockIdx.x * 1024 + threadIdx.x;  // float4 idx
    const float4 v0 = ((const float4*)A)[base];
    const float4 v1 = ((const float4*)A)[base + 512];
    ((uint2*)g_Af)[base] = make_uint2(h2u(__floats2half2_rn(v0.x, v0.y)),
                                      h2u(__floats2half2_rn(v0.z, v0.w)));
    ((uint2*)g_Af)[base + 512] = make_uint2(h2u(__floats2half2_rn(v1.x, v1.y)),
                                            h2u(__floats2half2_rn(v1.z, v1.w)));
}

// ---------------------------------------------------------------------------
// Pack B: Wh [k][n] fp32 -> g_Bf [n][k] fp16 (transpose)
// ---------------------------------------------------------------------------
__global__ void bpack_kernel(const float* __restrict__ Wh)
{
    const int n  = blockIdx.x;              // 0..511
    const int k4 = threadIdx.x * 4;         // 128 threads x 4 k
    __half2 lo = __floats2half2_rn(Wh[(size_t)(k4 + 0) * H_ + n], Wh[(size_t)(k4 + 1) * H_ + n]);
    __half2 hi = __floats2half2_rn(Wh[(size_t)(k4 + 2) * H_ + n], Wh[(size_t)(k4 + 3) * H_ + n]);
    *(uint2*)(g_Bf + (size_t)n * H_ + k4) = make_uint2(h2u(lo), h2u(hi));
}

// ---------------------------------------------------------------------------
// comb[b][n] = dec[b] @ Ws[:,n] + bs + bh + bc
// ---------------------------------------------------------------------------
__global__ void dec_comb_kernel(const float* __restrict__ dec,
                                const float* __restrict__ Ws,
                                const float* __restrict__ bs,
                                const float* __restrict__ bh,
                                const float* __restrict__ bc)
{
    const int b  = blockIdx.x;
    const int nh = blockIdx.y;
    const int tid = threadIdx.x;
    __shared__ float dh[H_];
    __shared__ float red[4][64];

    dh[tid]       = dec[b * H_ + tid];
    dh[tid + 256] = dec[b * H_ + tid + 256];
    __syncthreads();

    const int nl = tid & 63;
    const int n  = nh * 64 + nl;
    const int ks = tid >> 6;
    float acc = 0.f;
    #pragma unroll 8
    for (int h = ks * 128; h < ks * 128 + 128; ++h)
        acc = fmaf(dh[h], Ws[(size_t)h * H_ + n], acc);
    red[ks][nl] = acc;
    __syncthreads();
    if (ks == 0) {
        float s = red[0][nl] + red[1][nl] + red[2][nl] + red[3][nl];
        g_comb[b * H_ + n] = s + bs[n] + bh[n] + bc[n];
    }
}

// ---------------------------------------------------------------------------
// Main: 128x128x512 fp16 HMMA GEMM + fused tanh/v-dot epilogue
// grid (4 nc, 1024 m-tiles), 256 threads = 8 warps (warpM 0..1 x warpN 0..3)
// warp tile 64x32; k-chunk 64 (128B rows, XOR-swizzled); 3-stage cp.async
// pipeline with ONE __syncthreads per k-iter; 2 CTAs/SM.
// ---------------------------------------------------------------------------
#define MAT_BYTES   16384                 // 128 rows x 128B (swizzled, no pad)
#define STAGE_BYTES (2 * MAT_BYTES)       // 32768 (A|B)
#define OFF_COMB  (3 * STAGE_BYTES)       // 98304
#define OFF_WC    (OFF_COMB + 512)
#define OFF_VW    (OFF_WC + 512)
#define OFF_ERED  (OFF_VW + 512)          // 99840: 128 rows x 4 warpN floats
#define SMEM_DYN  (OFF_ERED + 128 * 4 * 4)   // 101888

// swizzled byte offset of (row r, 16B-chunk c) within a 128x128B matrix
#define SWZOFF(r, c) ((uint32_t)((r) * 128 + (((c) ^ ((r) & 7)) << 4)))

__global__ __launch_bounds__(256, 2)
void attn_hmma_kernel(const float* __restrict__ cov,
                      const float* __restrict__ Wc,
                      const float* __restrict__ v_w)
{
    extern __shared__ char sm[];
    const uint32_t sbase = smem_u32(sm);
    const int tid  = threadIdx.x;
    const int wid  = tid >> 5;
    const int lane = tid & 31;
    const int nc     = blockIdx.x;          // 0..3 (fast-varying: A-tile L2 reuse)
    const int mBase  = blockIdx.y * 128;
    const int ncBase = nc * 128;
    const int b      = mBase >> 11;

    // epilogue constants for this n-chunk (ordered before use by iter-0 sync)
    if (tid < 128) {
        ((float*)(sm + OFF_COMB))[tid] = g_comb[b * H_ + ncBase + tid];
        ((float*)(sm + OFF_WC))[tid]   = Wc[ncBase + tid];
        ((float*)(sm + OFF_VW))[tid]   = v_w[ncBase + tid];
    }

    // per-thread cp.async mapping: 2048 16B transfers/chunk, 8 per thread
    const char* srcs[8];
    uint32_t dsts[8];                      // stage-0 destinations
    #pragma unroll
    for (int p = 0; p < 8; ++p) {
        const int idx = p * 256 + tid;
        const int mat = idx >> 10;         // 0:A 1:B
        const int r   = (idx >> 3) & 127;
        const int cc  = idx & 7;
        const __half* g = (mat == 0) ? (g_Af + (size_t)(mBase + r) * H_)
                                     : (g_Bf + (size_t)(ncBase + r) * H_);
        srcs[p] = (const char*)(g + cc * 8);
        dsts[p] = sbase + mat * MAT_BYTES + SWZOFF(r, cc);
    }

    const int warpM = wid >> 2;            // 0..1 -> 64 rows
    const int warpN = wid & 3;             // 0..3 -> 32 cols

    // ldmatrix offsets (within a matrix; add stage/mat base later)
    uint32_t offA[4][4], offB[2][4];
    {
        const int rowA = warpM * 64 + (lane & 7) + ((lane >> 3) & 1) * 8;
        const int cA   = (lane >> 4);                   // 0..1
        #pragma unroll
        for (int mI = 0; mI < 4; ++mI)
            #pragma unroll
            for (int s = 0; s < 4; ++s)
                offA[mI][s] = SWZOFF(rowA + mI * 16, s * 2 + cA);
        const int rowB = warpN * 32 + (lane & 7) + ((lane & 16) ? 8 : 0);
        const int cB   = (lane >> 3) & 1;
        #pragma unroll
        for (int p = 0; p < 2; ++p)
            #pragma unroll
            for (int s = 0; s < 4; ++s)
                offB[p][s] = SWZOFF(rowB + p * 16, s * 2 + cB);
    }

    float acc[4][4][4];
    #pragma unroll
    for (int i = 0; i < 4; ++i)
        #pragma unroll
        for (int j = 0; j < 4; ++j)
            #pragma unroll
            for (int q = 0; q < 4; ++q) acc[i][j][q] = 0.f;

    // prologue: prefetch chunks 0 and 1 into stages 0 and 1
    #pragma unroll
    for (int p = 0; p < 8; ++p) cp16(dsts[p], srcs[p]);
    asm volatile("cp.async.commit_group;" ::: "memory");
    #pragma unroll
    for (int p = 0; p < 8; ++p) cp16(dsts[p] + STAGE_BYTES, srcs[p] + 128);
    asm volatile("cp.async.commit_group;" ::: "memory");

    int rdStage = 0;   // c % 3
    int wrStage = 2;   // (c+2) % 3
    #pragma unroll 1
    for (int c = 0; c < 8; ++c) {
        // chunk c guaranteed complete (groups complete in commit order)
        if (c < 7) asm volatile("cp.async.wait_group 1;" ::: "memory");
        else       asm volatile("cp.async.wait_group 0;" ::: "memory");
        __syncthreads();   // single barrier per iteration

        const uint32_t ab = sbase + rdStage * STAGE_BYTES;
        const uint32_t bb = ab + MAT_BYTES;

        #pragma unroll
        for (int s = 0; s < 4; ++s) {      // each s = 16 k
            uint32_t Af[4][4], Bf[2][4];
            #pragma unroll
            for (int p = 0; p < 2; ++p)    ldsm4(Bf[p], bb + offB[p][s]);
            #pragma unroll
            for (int mI = 0; mI < 4; ++mI) ldsm4(Af[mI], ab + offA[mI][s]);
            #pragma unroll
            for (int mI = 0; mI < 4; ++mI)
                #pragma unroll
                for (int nI = 0; nI < 4; ++nI)
                    mma_f16(acc[mI][nI], Af[mI], Bf[nI >> 1][(nI & 1) * 2], Bf[nI >> 1][(nI & 1) * 2 + 1]);
        }

        // prefetch chunk c+2 into wrStage = (c+2)%3 (safe: no reader left on it)
        if (c + 2 < 8) {
            const uint32_t soff = (uint32_t)wrStage * STAGE_BYTES;
            const int koff = (c + 2) * 128;
            #pragma unroll
            for (int p = 0; p < 8; ++p)
                cp16(dsts[p] + soff, srcs[p] + koff);
            asm volatile("cp.async.commit_group;" ::: "memory");
        }

        rdStage = (rdStage == 2) ? 0 : rdStage + 1;
        wrStage = (wrStage == 2) ? 0 : wrStage + 1;
    }

    // ---- fused epilogue: tanh + v-dot; shuffle-reduce the 4 col-threads,
    //      then smem-reduce the 4 warpN warps ----
    const float* sComb = (const float*)(sm + OFF_COMB);
    const float* sWc   = (const float*)(sm + OFF_WC);
    const float* sVw   = (const float*)(sm + OFF_VW);
    float* ered = (float*)(sm + OFF_ERED);    // [128 rows][4 warpN]

    #pragma unroll
    for (int mI = 0; mI < 4; ++mI) {
        const int mlo = warpM * 64 + mI * 16 + (lane >> 2);
        const float covlo = cov[mBase + mlo];
        const float covhi = cov[mBase + mlo + 8];
        float elo = 0.f, ehi = 0.f;
        #pragma unroll
        for (int nI = 0; nI < 4; ++nI) {
            #pragma unroll
            for (int t = 0; t < 2; ++t) {
                const int n = warpN * 32 + nI * 8 + (lane & 3) * 2 + t;
                const float cb = sComb[n], wc = sWc[n], vw = sVw[n];
                elo = fmaf(vw, tanh_acc(acc[mI][nI][t]     + cb + covlo * wc), elo);
                ehi = fmaf(vw, tanh_acc(acc[mI][nI][t + 2] + cb + covhi * wc), ehi);
            }
        }
        // reduce over lane&3 (the 4 column threads of each row)
        elo += __shfl_xor_sync(0xFFFFFFFFu, elo, 1);
        elo += __shfl_xor_sync(0xFFFFFFFFu, elo, 2);
        ehi += __shfl_xor_sync(0xFFFFFFFFu, ehi, 1);
        ehi += __shfl_xor_sync(0xFFFFFFFFu, ehi, 2);
        if ((lane & 3) == 0) {
            ered[mlo * 4 + warpN]       = elo;
            ered[(mlo + 8) * 4 + warpN] = ehi;
        }
    }
    __syncthreads();
    if (tid < 128) {
        const float s = ered[tid * 4] + ered[tid * 4 + 1] + ered[tid * 4 + 2] + ered[tid * 4 + 3];
        g_epart[nc * M_ + mBase + tid] = s;
    }
}

// ---------------------------------------------------------------------------
// Softmax over S=2048 per batch + coverage update (v_b shift-invariant)
// ---------------------------------------------------------------------------
__global__ __launch_bounds__(256)
void softmax_kernel(const float* __restrict__ cov, float* __restrict__ out)
{
    const int b   = blockIdx.x;
    const int tid = threadIdx.x;
    __shared__ float red[256];

    float local[8];
    float mx = -INFINITY;
    #pragma unroll
    for (int i = 0; i < 8; ++i) {
        const int idx = b * S_ + tid + i * 256;
        local[i] = g_epart[idx] + g_epart[M_ + idx] + g_epart[2 * M_ + idx] + g_epart[3 * M_ + idx];
        mx = fmaxf(mx, local[i]);
    }
    red[tid] = mx;
    __syncthreads();
    for (int s = 128; s > 0; s >>= 1) {
        if (tid < s) red[tid] = fmaxf(red[tid], red[tid + s]);
        __syncthreads();
    }
    const float m = red[0];
    __syncthreads();

    float sum = 0.f;
    #pragma unroll
    for (int i = 0; i < 8; ++i) {
        local[i] = __expf(local[i] - m);
        sum += local[i];
    }
    red[tid] = sum;
    __syncthreads();
    for (int s = 128; s > 0; s >>= 1) {
        if (tid < s) red[tid] += red[tid + s];
        __syncthreads();
    }
    const float inv = 1.0f / red[0];

    #pragma unroll
    for (int i = 0; i < 8; ++i) {
        const int idx = b * S_ + tid + i * 256;
        const float a = local[i] * inv;
        out[idx]      = a;
        out[M_ + idx] = cov[idx] + a;
    }
}

// ---------------------------------------------------------------------------
extern "C" void kernel_launch(void* const* d_in, const int* in_sizes, int n_in,
                              void* d_out, int out_size)
{
    const float* enc = (const float*)d_in[0];
    const float* dec = (const float*)d_in[1];
    const float* cov = (const float*)d_in[2];
    const float* Wh  = (const float*)d_in[3];
    const float* bh  = (const float*)d_in[4];
    const float* Ws  = (const float*)d_in[5];
    const float* bs  = (const float*)d_in[6];
    const float* Wc  = (const float*)d_in[7];
    const float* bc  = (const float*)d_in[8];
    const float* v_w = (const float*)d_in[9];
    float* out = (float*)d_out;

    cudaFuncSetAttribute(attn_hmma_kernel,
                         cudaFuncAttributeMaxDynamicSharedMemorySize, SMEM_DYN);

    apack_kernel<<<M_ * H_ / 4 / 1024, 512>>>(enc);
    bpack_kernel<<<H_, 128>>>(Wh);
    dec_comb_kernel<<<dim3(B_, 8), 256>>>(dec, Ws, bs, bh, bc);
    attn_hmma_kernel<<<dim3(4, M_ / 128), 256, SMEM_DYN>>>(cov, Wc, v_w);
    softmax_kernel<<<B_, 256>>>(cov, out);
}

// round 14
// speedup vs baseline: 1.1508x; 1.0360x over previous
#include <cuda_runtime.h>
#include <cuda_fp16.h>
#include <math.h>
#include <stdint.h>

#define B_  64
#define S_  2048
#define H_  512
#define M_  (B_ * S_)

// ---------------- device scratch (no allocs allowed) ----------------
__device__ __half g_Af[(size_t)M_ * H_];   // 128 MB enc fp16
__device__ __half g_Bf[H_ * H_];           // Wh^T fp16 [n][k]
__device__ float g_comb[B_ * H_];          // dec@Ws + bs + bh + bc
__device__ float g_epart[4 * M_];          // per-nc partial e sums

// ---------------- helpers ----------------
__device__ __forceinline__ uint32_t smem_u32(const void* p) {
    uint32_t a;
    asm("{ .reg .u64 t; cvta.to.shared.u64 t, %1; cvt.u32.u64 %0, t; }" : "=r"(a) : "l"(p));
    return a;
}
// accurate tanh: 2 MUFU, rel err ~1e-7, saturates correctly
__device__ __forceinline__ float tanh_acc(float x) {
    float e = __expf(2.0f * x);
    return 1.0f - __fdividef(2.0f, e + 1.0f);
}
__device__ __forceinline__ void ldsm4(uint32_t* r, uint32_t addr) {
    asm volatile("ldmatrix.sync.aligned.m8n8.x4.shared.b16 {%0,%1,%2,%3}, [%4];"
                 : "=r"(r[0]), "=r"(r[1]), "=r"(r[2]), "=r"(r[3]) : "r"(addr));
}
__device__ __forceinline__ void mma_f16(float* c, const uint32_t* a, uint32_t b0, uint32_t b1) {
    asm volatile(
        "mma.sync.aligned.m16n8k16.row.col.f32.f16.f16.f32 "
        "{%0,%1,%2,%3},{%4,%5,%6,%7},{%8,%9},{%0,%1,%2,%3};"
        : "+f"(c[0]), "+f"(c[1]), "+f"(c[2]), "+f"(c[3])
        : "r"(a[0]), "r"(a[1]), "r"(a[2]), "r"(a[3]), "r"(b0), "r"(b1));
}
__device__ __forceinline__ void cp16(uint32_t dst, const void* src) {
    asm volatile("cp.async.cg.shared.global [%0], [%1], 16;" :: "r"(dst), "l"(src));
}
__device__ __forceinline__ uint32_t h2u(__half2 h) { return *(uint32_t*)&h; }

// ---------------------------------------------------------------------------
// Merged prologue: apack (blocks 0..16383), bpack (16384..16639),
// dec_comb (16640..17151). All independent writes, one launch.
// ---------------------------------------------------------------------------
__global__ __launch_bounds__(256)
void prologue_kernel(const float* __restrict__ enc,
                     const float* __restrict__ Wh,
                     const float* __restrict__ dec,
                     const float* __restrict__ Ws,
                     const float* __restrict__ bs,
                     const float* __restrict__ bh,
                     const float* __restrict__ bc)
{
    const int bid = blockIdx.x;
    const int tid = threadIdx.x;
    __shared__ float dh[H_];
    __shared__ float red[4][64];

    if (bid < 16384) {
        // ---- apack: enc fp32 -> g_Af fp16, 4 float4 per thread ----
        const size_t base = (size_t)bid * 1024 + tid;
        #pragma unroll
        for (int j = 0; j < 4; ++j) {
            const size_t i = base + j * 256;
            const float4 v = ((const float4*)enc)[i];
            ((uint2*)g_Af)[i] = make_uint2(h2u(__floats2half2_rn(v.x, v.y)),
                                           h2u(__floats2half2_rn(v.z, v.w)));
        }
    } else if (bid < 16384 + 256) {
        // ---- bpack: Wh [k][n] -> g_Bf [n][k] fp16 (transpose), 2 n per block ----
        const int n  = (bid - 16384) * 2 + (tid >> 7);
        const int k4 = (tid & 127) * 4;
        __half2 lo = __floats2half2_rn(Wh[(size_t)(k4 + 0) * H_ + n], Wh[(size_t)(k4 + 1) * H_ + n]);
        __half2 hi = __floats2half2_rn(Wh[(size_t)(k4 + 2) * H_ + n], Wh[(size_t)(k4 + 3) * H_ + n]);
        *(uint2*)(g_Bf + (size_t)n * H_ + k4) = make_uint2(h2u(lo), h2u(hi));
    } else {
        // ---- dec_comb: comb[b][n] = dec[b] @ Ws[:,n] + bs + bh + bc ----
        const int id = bid - 16640;        // 0..511
        const int b  = id >> 3;
        const int nh = id & 7;

        dh[tid]       = dec[b * H_ + tid];
        dh[tid + 256] = dec[b * H_ + tid + 256];
        __syncthreads();

        const int nl = tid & 63;
        const int n  = nh * 64 + nl;
        const int ks = tid >> 6;
        float acc = 0.f;
        #pragma unroll 8
        for (int h = ks * 128; h < ks * 128 + 128; ++h)
            acc = fmaf(dh[h], Ws[(size_t)h * H_ + n], acc);
        red[ks][nl] = acc;
        __syncthreads();
        if (ks == 0) {
            float s = red[0][nl] + red[1][nl] + red[2][nl] + red[3][nl];
            g_comb[b * H_ + n] = s + bs[n] + bh[n] + bc[n];
        }
    }
}

// ---------------------------------------------------------------------------
// Main: 128x128x512 fp16 HMMA GEMM + fused tanh/v-dot epilogue
// grid (4 nc, 1024 m-tiles), 256 threads = 8 warps (warpM 0..1 x warpN 0..3)
// warp tile 64x32; k-chunk 64 (128B rows, XOR-swizzled); 3-stage cp.async
// pipeline, one barrier per iter; s-loop fragment rotation; 2 CTAs/SM.
// ---------------------------------------------------------------------------
#define MAT_BYTES   16384                 // 128 rows x 128B (swizzled, no pad)
#define STAGE_BYTES (2 * MAT_BYTES)       // 32768 (A|B)
#define OFF_COMB  (3 * STAGE_BYTES)       // 98304
#define OFF_WC    (OFF_COMB + 512)
#define OFF_VW    (OFF_WC + 512)
#define OFF_ERED  (OFF_VW + 512)          // 99840: 128 rows x 4 warpN floats
#define SMEM_DYN  (OFF_ERED + 128 * 4 * 4)   // 101888

// swizzled byte offset of (row r, 16B-chunk c) within a 128x128B matrix
#define SWZOFF(r, c) ((uint32_t)((r) * 128 + ((((c) ^ ((r) & 7))) << 4)))

__global__ __launch_bounds__(256, 2)
void attn_hmma_kernel(const float* __restrict__ cov,
                      const float* __restrict__ Wc,
                      const float* __restrict__ v_w)
{
    extern __shared__ char sm[];
    const uint32_t sbase = smem_u32(sm);
    const int tid  = threadIdx.x;
    const int wid  = tid >> 5;
    const int lane = tid & 31;
    const int nc     = blockIdx.x;          // 0..3 (fast-varying: A-tile L2 reuse)
    const int mBase  = blockIdx.y * 128;
    const int ncBase = nc * 128;
    const int b      = mBase >> 11;

    // epilogue constants for this n-chunk (ordered before use by iter-0 sync)
    if (tid < 128) {
        ((float*)(sm + OFF_COMB))[tid] = g_comb[b * H_ + ncBase + tid];
        ((float*)(sm + OFF_WC))[tid]   = Wc[ncBase + tid];
        ((float*)(sm + OFF_VW))[tid]   = v_w[ncBase + tid];
    }

    // cp.async bases: thread covers rows (tid>>3)+32p, 16B-chunk tid&7
    // p in 0..3 per matrix; row step 32 preserves r&7 -> same swizzle term.
    const uint32_t dstA0 = sbase + SWZOFF(tid >> 3, tid & 7);
    const uint32_t dstB0 = dstA0 + MAT_BYTES;
    const char* srcA0 = (const char*)(g_Af + (size_t)(mBase + (tid >> 3)) * H_) + (tid & 7) * 16;
    const char* srcB0 = (const char*)(g_Bf + (size_t)(ncBase + (tid >> 3)) * H_) + (tid & 7) * 16;

#define CP_CHUNK(kc, stg) do { \
    const uint32_t _so = (uint32_t)(stg) * STAGE_BYTES; \
    const int _ko = (kc) * 128; \
    _Pragma("unroll") \
    for (int _p = 0; _p < 4; ++_p) \
        cp16(dstA0 + _so + _p * 4096, srcA0 + _p * 32768 + _ko); \
    _Pragma("unroll") \
    for (int _p = 0; _p < 4; ++_p) \
        cp16(dstB0 + _so + _p * 4096, srcB0 + _p * 32768 + _ko); \
    asm volatile("cp.async.commit_group;" ::: "memory"); \
} while (0)

    const int warpM = wid >> 2;            // 0..1 -> 64 rows
    const int warpN = wid & 3;             // 0..3 -> 32 cols

    // per-s ldsm base offsets; mI/p add a linear 2048B (swizzle term invariant)
    uint32_t offA[4], offB[4];
    {
        const int rowA = warpM * 64 + (lane & 7) + ((lane >> 3) & 1) * 8;
        const int cA   = (lane >> 4);                   // 0..1
        #pragma unroll
        for (int s = 0; s < 4; ++s)
            offA[s] = SWZOFF(rowA, s * 2 + cA);
        const int rowB = warpN * 32 + (lane & 7) + ((lane & 16) ? 8 : 0);
        const int cB   = (lane >> 3) & 1;
        #pragma unroll
        for (int s = 0; s < 4; ++s)
            offB[s] = SWZOFF(rowB, s * 2 + cB);
    }

    float acc[4][4][4];
    #pragma unroll
    for (int i = 0; i < 4; ++i)
        #pragma unroll
        for (int j = 0; j < 4; ++j)
            #pragma unroll
            for (int q = 0; q < 4; ++q) acc[i][j][q] = 0.f;

    // prologue: prefetch chunks 0 and 1 into stages 0 and 1
    CP_CHUNK(0, 0);
    CP_CHUNK(1, 1);

    int rdStage = 0;   // c % 3
    int wrStage = 2;   // (c+2) % 3
    #pragma unroll 1
    for (int c = 0; c < 8; ++c) {
        // chunk c guaranteed complete (groups complete in commit order)
        if (c < 7) asm volatile("cp.async.wait_group 1;" ::: "memory");
        else       asm volatile("cp.async.wait_group 0;" ::: "memory");
        __syncthreads();   // single barrier per iteration

        // issue prefetch of chunk c+2 FIRST so it overlaps the MMA block
        if (c + 2 < 8) CP_CHUNK(c + 2, wrStage);

        const uint32_t ab = sbase + rdStage * STAGE_BYTES;
        const uint32_t bb = ab + MAT_BYTES;

        // fragment rotation: preload s=0; per s run MMA then load s+1 into
        // the same regs (WAR on regs enforces the rotation order)
        uint32_t Af[4][4], Bf[2][4];
        #pragma unroll
        for (int p = 0; p < 2; ++p)    ldsm4(Bf[p], bb + offB[0] + p * 2048);
        #pragma unroll
        for (int mI = 0; mI < 4; ++mI) ldsm4(Af[mI], ab + offA[0] + mI * 2048);

        #pragma unroll
        for (int s = 0; s < 4; ++s) {
            #pragma unroll
            for (int mI = 0; mI < 4; ++mI)
                #pragma unroll
                for (int nI = 0; nI < 4; ++nI)
                    mma_f16(acc[mI][nI], Af[mI], Bf[nI >> 1][(nI & 1) * 2], Bf[nI >> 1][(nI & 1) * 2 + 1]);
            if (s < 3) {
                #pragma unroll
                for (int p = 0; p < 2; ++p)    ldsm4(Bf[p], bb + offB[s + 1] + p * 2048);
                #pragma unroll
                for (int mI = 0; mI < 4; ++mI) ldsm4(Af[mI], ab + offA[s + 1] + mI * 2048);
            }
        }

        rdStage = (rdStage == 2) ? 0 : rdStage + 1;
        wrStage = (wrStage == 2) ? 0 : wrStage + 1;
    }
#undef CP_CHUNK

    // ---- fused epilogue: tanh + v-dot; shuffle-reduce the 4 col-threads,
    //      then smem-reduce the 4 warpN warps ----
    const float* sComb = (const float*)(sm + OFF_COMB);
    const float* sWc   = (const float*)(sm + OFF_WC);
    const float* sVw   = (const float*)(sm + OFF_VW);
    float* ered = (float*)(sm + OFF_ERED);    // [128 rows][4 warpN]

    #pragma unroll
    for (int mI = 0; mI < 4; ++mI) {
        const int mlo = warpM * 64 + mI * 16 + (lane >> 2);
        const float covlo = cov[mBase + mlo];
        const float covhi = cov[mBase + mlo + 8];
        float elo = 0.f, ehi = 0.f;
        #pragma unroll
        for (int nI = 0; nI < 4; ++nI) {
            #pragma unroll
            for (int t = 0; t < 2; ++t) {
                const int n = warpN * 32 + nI * 8 + (lane & 3) * 2 + t;
                const float cb = sComb[n], wc = sWc[n], vw = sVw[n];
                elo = fmaf(vw, tanh_acc(acc[mI][nI][t]     + cb + covlo * wc), elo);
                ehi = fmaf(vw, tanh_acc(acc[mI][nI][t + 2] + cb + covhi * wc), ehi);
            }
        }
        // reduce over lane&3 (the 4 column threads of each row)
        elo += __shfl_xor_sync(0xFFFFFFFFu, elo, 1);
        elo += __shfl_xor_sync(0xFFFFFFFFu, elo, 2);
        ehi += __shfl_xor_sync(0xFFFFFFFFu, ehi, 1);
        ehi += __shfl_xor_sync(0xFFFFFFFFu, ehi, 2);
        if ((lane & 3) == 0) {
            ered[mlo * 4 + warpN]       = elo;
            ered[(mlo + 8) * 4 + warpN] = ehi;
        }
    }
    __syncthreads();
    if (tid < 128) {
        const float s = ered[tid * 4] + ered[tid * 4 + 1] + ered[tid * 4 + 2] + ered[tid * 4 + 3];
        g_epart[nc * M_ + mBase + tid] = s;
    }
}

// ---------------------------------------------------------------------------
// Softmax over S=2048 per batch + coverage update (v_b shift-invariant)
// ---------------------------------------------------------------------------
__global__ __launch_bounds__(256)
void softmax_kernel(const float* __restrict__ cov, float* __restrict__ out)
{
    const int b   = blockIdx.x;
    const int tid = threadIdx.x;
    __shared__ float red[256];

    float local[8];
    float mx = -INFINITY;
    #pragma unroll
    for (int i = 0; i < 8; ++i) {
        const int idx = b * S_ + tid + i * 256;
        local[i] = g_epart[idx] + g_epart[M_ + idx] + g_epart[2 * M_ + idx] + g_epart[3 * M_ + idx];
        mx = fmaxf(mx, local[i]);
    }
    red[tid] = mx;
    __syncthreads();
    for (int s = 128; s > 0; s >>= 1) {
        if (tid < s) red[tid] = fmaxf(red[tid], red[tid + s]);
        __syncthreads();
    }
    const float m = red[0];
    __syncthreads();

    float sum = 0.f;
    #pragma unroll
    for (int i = 0; i < 8; ++i) {
        local[i] = __expf(local[i] - m);
        sum += local[i];
    }
    red[tid] = sum;
    __syncthreads();
    for (int s = 128; s > 0; s >>= 1) {
        if (tid < s) red[tid] += red[tid + s];
        __syncthreads();
    }
    const float inv = 1.0f / red[0];

    #pragma unroll
    for (int i = 0; i < 8; ++i) {
        const int idx = b * S_ + tid + i * 256;
        const float a = local[i] * inv;
        out[idx]      = a;
        out[M_ + idx] = cov[idx] + a;
    }
}

// ---------------------------------------------------------------------------
extern "C" void kernel_launch(void* const* d_in, const int* in_sizes, int n_in,
                              void* d_out, int out_size)
{
    const float* enc = (const float*)d_in[0];
    const float* dec = (const float*)d_in[1];
    const float* cov = (const float*)d_in[2];
    const float* Wh  = (const float*)d_in[3];
    const float* bh  = (const float*)d_in[4];
    const float* Ws  = (const float*)d_in[5];
    const float* bs  = (const float*)d_in[6];
    const float* Wc  = (const float*)d_in[7];
    const float* bc  = (const float*)d_in[8];
    const float* v_w = (const float*)d_in[9];
    float* out = (float*)d_out;

    cudaFuncSetAttribute(attn_hmma_kernel,
                         cudaFuncAttributeMaxDynamicSharedMemorySize, SMEM_DYN);

    prologue_kernel<<<17152, 256>>>(enc, Wh, dec, Ws, bs, bh, bc);
    attn_hmma_kernel<<<dim3(4, M_ / 128), 256, SMEM_DYN>>>(cov, Wc, v_w);
    softmax_kernel<<<B_, 256>>>(cov, out);
}

// round 15
// speedup vs baseline: 1.2149x; 1.0557x over previous
#include <cuda_runtime.h>
#include <cuda_fp16.h>
#include <math.h>
#include <stdint.h>

#define B_  64
#define S_  2048
#define H_  512
#define M_  (B_ * S_)

// ---------------- device scratch (no allocs allowed) ----------------
__device__ __half g_Af[(size_t)M_ * H_];   // 128 MB enc fp16
__device__ __half g_Bf[H_ * H_];           // Wh^T fp16 [n][k]
__device__ float g_comb[B_ * H_];          // dec@Ws + bs + bh + bc
__device__ float g_epart[4 * M_];          // per-nc partial e sums

// ---------------- helpers ----------------
__device__ __forceinline__ uint32_t smem_u32(const void* p) {
    uint32_t a;
    asm("{ .reg .u64 t; cvta.to.shared.u64 t, %1; cvt.u32.u64 %0, t; }" : "=r"(a) : "l"(p));
    return a;
}
// accurate tanh: 2 MUFU, rel err ~1e-7, saturates correctly
__device__ __forceinline__ float tanh_acc(float x) {
    float e = __expf(2.0f * x);
    return 1.0f - __fdividef(2.0f, e + 1.0f);
}
__device__ __forceinline__ void ldsm4(uint32_t* r, uint32_t addr) {
    asm volatile("ldmatrix.sync.aligned.m8n8.x4.shared.b16 {%0,%1,%2,%3}, [%4];"
                 : "=r"(r[0]), "=r"(r[1]), "=r"(r[2]), "=r"(r[3]) : "r"(addr));
}
__device__ __forceinline__ void mma_f16(float* c, const uint32_t* a, uint32_t b0, uint32_t b1) {
    asm volatile(
        "mma.sync.aligned.m16n8k16.row.col.f32.f16.f16.f32 "
        "{%0,%1,%2,%3},{%4,%5,%6,%7},{%8,%9},{%0,%1,%2,%3};"
        : "+f"(c[0]), "+f"(c[1]), "+f"(c[2]), "+f"(c[3])
        : "r"(a[0]), "r"(a[1]), "r"(a[2]), "r"(a[3]), "r"(b0), "r"(b1));
}
__device__ __forceinline__ void cp16(uint32_t dst, const void* src) {
    asm volatile("cp.async.cg.shared.global [%0], [%1], 16;" :: "r"(dst), "l"(src));
}
__device__ __forceinline__ uint32_t h2u(__half2 h) { return *(uint32_t*)&h; }

// ---------------------------------------------------------------------------
// Merged prologue: apack (blocks 0..16383), bpack (16384..16639),
// dec_comb (16640..17151). All independent writes, one launch.
// ---------------------------------------------------------------------------
__global__ __launch_bounds__(256)
void prologue_kernel(const float* __restrict__ enc,
                     const float* __restrict__ Wh,
                     const float* __restrict__ dec,
                     const float* __restrict__ Ws,
                     const float* __restrict__ bs,
                     const float* __restrict__ bh,
                     const float* __restrict__ bc)
{
    const int bid = blockIdx.x;
    const int tid = threadIdx.x;
    __shared__ float dh[H_];
    __shared__ float red[4][64];

    if (bid < 16384) {
        // ---- apack: enc fp32 -> g_Af fp16; 2 adjacent float4 -> 1 uint4 store
        // thread covers float4 indices base, base+1 (adjacent) for j=0,1
        const size_t base = (size_t)bid * 1024 + tid * 2;
        #pragma unroll
        for (int j = 0; j < 2; ++j) {
            const size_t i = base + j * 512;
            const float4 v0 = ((const float4*)enc)[i];
            const float4 v1 = ((const float4*)enc)[i + 1];
            uint4 o;
            o.x = h2u(__floats2half2_rn(v0.x, v0.y));
            o.y = h2u(__floats2half2_rn(v0.z, v0.w));
            o.z = h2u(__floats2half2_rn(v1.x, v1.y));
            o.w = h2u(__floats2half2_rn(v1.z, v1.w));
            ((uint4*)g_Af)[i >> 1] = o;
        }
    } else if (bid < 16384 + 256) {
        // ---- bpack: Wh [k][n] -> g_Bf [n][k] fp16 (transpose), 2 n per block ----
        const int n  = (bid - 16384) * 2 + (tid >> 7);
        const int k4 = (tid & 127) * 4;
        __half2 lo = __floats2half2_rn(Wh[(size_t)(k4 + 0) * H_ + n], Wh[(size_t)(k4 + 1) * H_ + n]);
        __half2 hi = __floats2half2_rn(Wh[(size_t)(k4 + 2) * H_ + n], Wh[(size_t)(k4 + 3) * H_ + n]);
        *(uint2*)(g_Bf + (size_t)n * H_ + k4) = make_uint2(h2u(lo), h2u(hi));
    } else {
        // ---- dec_comb: comb[b][n] = dec[b] @ Ws[:,n] + bs + bh + bc ----
        const int id = bid - 16640;        // 0..511
        const int b  = id >> 3;
        const int nh = id & 7;

        dh[tid]       = dec[b * H_ + tid];
        dh[tid + 256] = dec[b * H_ + tid + 256];
        __syncthreads();

        const int nl = tid & 63;
        const int n  = nh * 64 + nl;
        const int ks = tid >> 6;
        float acc = 0.f;
        #pragma unroll 8
        for (int h = ks * 128; h < ks * 128 + 128; ++h)
            acc = fmaf(dh[h], Ws[(size_t)h * H_ + n], acc);
        red[ks][nl] = acc;
        __syncthreads();
        if (ks == 0) {
            float s = red[0][nl] + red[1][nl] + red[2][nl] + red[3][nl];
            g_comb[b * H_ + n] = s + bs[n] + bh[n] + bc[n];
        }
    }
}

// ---------------------------------------------------------------------------
// Main: 128x128x512 fp16 HMMA GEMM + fused tanh/v-dot epilogue
// grid (4 nc, 1024 m-tiles), 256 threads = 8 warps (warpM 0..1 x warpN 0..3)
// warp tile 64x32; k-chunk 64 (128B rows, XOR-swizzled); 3-stage cp.async
// pipeline, FULLY UNROLLED k-loop (compile-time stages); 2 CTAs/SM.
// ---------------------------------------------------------------------------
#define MAT_BYTES   16384                 // 128 rows x 128B (swizzled, no pad)
#define STAGE_BYTES (2 * MAT_BYTES)       // 32768 (A|B)
#define OFF_COMB  (3 * STAGE_BYTES)       // 98304
#define OFF_WC    (OFF_COMB + 512)
#define OFF_VW    (OFF_WC + 512)
#define OFF_ERED  (OFF_VW + 512)          // 99840: 128 rows x 4 warpN floats
#define SMEM_DYN  (OFF_ERED + 128 * 4 * 4)   // 101888

// swizzled byte offset of (row r, 16B-chunk c) within a 128x128B matrix
#define SWZOFF(r, c) ((uint32_t)((r) * 128 + ((((c) ^ ((r) & 7))) << 4)))

__global__ __launch_bounds__(256, 2)
void attn_hmma_kernel(const float* __restrict__ cov,
                      const float* __restrict__ Wc,
                      const float* __restrict__ v_w)
{
    extern __shared__ char sm[];
    const uint32_t sbase = smem_u32(sm);
    const int tid  = threadIdx.x;
    const int wid  = tid >> 5;
    const int lane = tid & 31;
    const int nc     = blockIdx.x;          // 0..3 (fast-varying: A-tile L2 reuse)
    const int mBase  = blockIdx.y * 128;
    const int ncBase = nc * 128;
    const int b      = mBase >> 11;

    // epilogue constants for this n-chunk (ordered before use by iter-0 sync)
    if (tid < 128) {
        ((float*)(sm + OFF_COMB))[tid] = g_comb[b * H_ + ncBase + tid];
        ((float*)(sm + OFF_WC))[tid]   = Wc[ncBase + tid];
        ((float*)(sm + OFF_VW))[tid]   = v_w[ncBase + tid];
    }

    // cp.async bases: thread covers rows (tid>>3)+32p, 16B-chunk tid&7
    // p in 0..3 per matrix; row step 32 preserves r&7 -> same swizzle term.
    const uint32_t dstA0 = sbase + SWZOFF(tid >> 3, tid & 7);
    const uint32_t dstB0 = dstA0 + MAT_BYTES;
    const char* srcA0 = (const char*)(g_Af + (size_t)(mBase + (tid >> 3)) * H_) + (tid & 7) * 16;
    const char* srcB0 = (const char*)(g_Bf + (size_t)(ncBase + (tid >> 3)) * H_) + (tid & 7) * 16;

#define CP_CHUNK(kc, stg) do { \
    const uint32_t _so = (uint32_t)(stg) * STAGE_BYTES; \
    const int _ko = (kc) * 128; \
    _Pragma("unroll") \
    for (int _p = 0; _p < 4; ++_p) \
        cp16(dstA0 + _so + _p * 4096, srcA0 + _p * 32768 + _ko); \
    _Pragma("unroll") \
    for (int _p = 0; _p < 4; ++_p) \
        cp16(dstB0 + _so + _p * 4096, srcB0 + _p * 32768 + _ko); \
    asm volatile("cp.async.commit_group;" ::: "memory"); \
} while (0)

    const int warpM = wid >> 2;            // 0..1 -> 64 rows
    const int warpN = wid & 3;             // 0..3 -> 32 cols

    // per-s ldsm base offsets; mI/p add a linear 2048B (swizzle term invariant)
    uint32_t offA[4], offB[4];
    {
        const int rowA = warpM * 64 + (lane & 7) + ((lane >> 3) & 1) * 8;
        const int cA   = (lane >> 4);                   // 0..1
        #pragma unroll
        for (int s = 0; s < 4; ++s)
            offA[s] = SWZOFF(rowA, s * 2 + cA);
        const int rowB = warpN * 32 + (lane & 7) + ((lane & 16) ? 8 : 0);
        const int cB   = (lane >> 3) & 1;
        #pragma unroll
        for (int s = 0; s < 4; ++s)
            offB[s] = SWZOFF(rowB, s * 2 + cB);
    }

    float acc[4][4][4];
    #pragma unroll
    for (int i = 0; i < 4; ++i)
        #pragma unroll
        for (int j = 0; j < 4; ++j)
            #pragma unroll
            for (int q = 0; q < 4; ++q) acc[i][j][q] = 0.f;

    // prologue: prefetch chunks 0 and 1 into stages 0 and 1
    CP_CHUNK(0, 0);
    CP_CHUNK(1, 1);

    #pragma unroll
    for (int c = 0; c < 8; ++c) {
        // chunk c guaranteed complete (groups complete in commit order)
        if (c < 7) asm volatile("cp.async.wait_group 1;" ::: "memory");
        else       asm volatile("cp.async.wait_group 0;" ::: "memory");
        __syncthreads();   // single barrier per iteration

        // issue prefetch of chunk c+2 FIRST so it overlaps the MMA block
        if (c + 2 < 8) CP_CHUNK(c + 2, (c + 2) % 3);

        const uint32_t ab = sbase + (c % 3) * STAGE_BYTES;
        const uint32_t bb = ab + MAT_BYTES;

        // fragment rotation: preload s=0; per s run MMA then load s+1 into
        // the same regs (WAR on regs enforces the rotation order)
        uint32_t Af[4][4], Bf[2][4];
        #pragma unroll
        for (int p = 0; p < 2; ++p)    ldsm4(Bf[p], bb + offB[0] + p * 2048);
        #pragma unroll
        for (int mI = 0; mI < 4; ++mI) ldsm4(Af[mI], ab + offA[0] + mI * 2048);

        #pragma unroll
        for (int s = 0; s < 4; ++s) {
            #pragma unroll
            for (int mI = 0; mI < 4; ++mI)
                #pragma unroll
                for (int nI = 0; nI < 4; ++nI)
                    mma_f16(acc[mI][nI], Af[mI], Bf[nI >> 1][(nI & 1) * 2], Bf[nI >> 1][(nI & 1) * 2 + 1]);
            if (s < 3) {
                #pragma unroll
                for (int p = 0; p < 2; ++p)    ldsm4(Bf[p], bb + offB[s + 1] + p * 2048);
                #pragma unroll
                for (int mI = 0; mI < 4; ++mI) ldsm4(Af[mI], ab + offA[s + 1] + mI * 2048);
            }
        }
    }
#undef CP_CHUNK

    // ---- fused epilogue: tanh + v-dot; shuffle-reduce the 4 col-threads,
    //      then smem-reduce the 4 warpN warps ----
    const float* sComb = (const float*)(sm + OFF_COMB);
    const float* sWc   = (const float*)(sm + OFF_WC);
    const float* sVw   = (const float*)(sm + OFF_VW);
    float* ered = (float*)(sm + OFF_ERED);    // [128 rows][4 warpN]

    #pragma unroll
    for (int mI = 0; mI < 4; ++mI) {
        const int mlo = warpM * 64 + mI * 16 + (lane >> 2);
        const float covlo = cov[mBase + mlo];
        const float covhi = cov[mBase + mlo + 8];
        float elo = 0.f, ehi = 0.f;
        #pragma unroll
        for (int nI = 0; nI < 4; ++nI) {
            #pragma unroll
            for (int t = 0; t < 2; ++t) {
                const int n = warpN * 32 + nI * 8 + (lane & 3) * 2 + t;
                const float cb = sComb[n], wc = sWc[n], vw = sVw[n];
                elo = fmaf(vw, tanh_acc(acc[mI][nI][t]     + cb + covlo * wc), elo);
                ehi = fmaf(vw, tanh_acc(acc[mI][nI][t + 2] + cb + covhi * wc), ehi);
            }
        }
        // reduce over lane&3 (the 4 column threads of each row)
        elo += __shfl_xor_sync(0xFFFFFFFFu, elo, 1);
        elo += __shfl_xor_sync(0xFFFFFFFFu, elo, 2);
        ehi += __shfl_xor_sync(0xFFFFFFFFu, ehi, 1);
        ehi += __shfl_xor_sync(0xFFFFFFFFu, ehi, 2);
        if ((lane & 3) == 0) {
            ered[mlo * 4 + warpN]       = elo;
            ered[(mlo + 8) * 4 + warpN] = ehi;
        }
    }
    __syncthreads();
    if (tid < 128) {
        const float s = ered[tid * 4] + ered[tid * 4 + 1] + ered[tid * 4 + 2] + ered[tid * 4 + 3];
        g_epart[nc * M_ + mBase + tid] = s;
    }
}

// ---------------------------------------------------------------------------
// Softmax over S=2048 per batch + coverage update (v_b shift-invariant)
// ---------------------------------------------------------------------------
__global__ __launch_bounds__(256)
void softmax_kernel(const float* __restrict__ cov, float* __restrict__ out)
{
    const int b   = blockIdx.x;
    const int tid = threadIdx.x;
    __shared__ float red[256];

    float local[8];
    float mx = -INFINITY;
    #pragma unroll
    for (int i = 0; i < 8; ++i) {
        const int idx = b * S_ + tid + i * 256;
        local[i] = g_epart[idx] + g_epart[M_ + idx] + g_epart[2 * M_ + idx] + g_epart[3 * M_ + idx];
        mx = fmaxf(mx, local[i]);
    }
    red[tid] = mx;
    __syncthreads();
    for (int s = 128; s > 0; s >>= 1) {
        if (tid < s) red[tid] = fmaxf(red[tid], red[tid + s]);
        __syncthreads();
    }
    const float m = red[0];
    __syncthreads();

    float sum = 0.f;
    #pragma unroll
    for (int i = 0; i < 8; ++i) {
        local[i] = __expf(local[i] - m);
        sum += local[i];
    }
    red[tid] = sum;
    __syncthreads();
    for (int s = 128; s > 0; s >>= 1) {
        if (tid < s) red[tid] += red[tid + s];
        __syncthreads();
    }
    const float inv = 1.0f / red[0];

    #pragma unroll
    for (int i = 0; i < 8; ++i) {
        const int idx = b * S_ + tid + i * 256;
        const float a = local[i] * inv;
        out[idx]      = a;
        out[M_ + idx] = cov[idx] + a;
    }
}

// ---------------------------------------------------------------------------
extern "C" void kernel_launch(void* const* d_in, const int* in_sizes, int n_in,
                              void* d_out, int out_size)
{
    const float* enc = (const float*)d_in[0];
    const float* dec = (const float*)d_in[1];
    const float* cov = (const float*)d_in[2];
    const float* Wh  = (const float*)d_in[3];
    const float* bh  = (const float*)d_in[4];
    const float* Ws  = (const float*)d_in[5];
    const float* bs  = (const float*)d_in[6];
    const float* Wc  = (const float*)d_in[7];
    const float* bc  = (const float*)d_in[8];
    const float* v_w = (const float*)d_in[9];
    float* out = (float*)d_out;

    cudaFuncSetAttribute(attn_hmma_kernel,
                         cudaFuncAttributeMaxDynamicSharedMemorySize, SMEM_DYN);

    prologue_kernel<<<17152, 256>>>(enc, Wh, dec, Ws, bs, bh, bc);
    attn_hmma_kernel<<<dim3(4, M_ / 128), 256, SMEM_DYN>>>(cov, Wc, v_w);
    softmax_kernel<<<B_, 256>>>(cov, out);
}

// round 16
// speedup vs baseline: 1.2270x; 1.0099x over previous
#include <cuda_runtime.h>
#include <cuda_fp16.h>
#include <math.h>
#include <stdint.h>

#define B_  64
#define S_  2048
#define H_  512
#define M_  (B_ * S_)

// ---------------- device scratch (no allocs allowed) ----------------
__device__ __half g_Af[(size_t)M_ * H_];   // 128 MB enc fp16
__device__ __half g_Bf[H_ * H_];           // Wh^T fp16 [n][k]
__device__ float g_comb[B_ * H_];          // dec@Ws + bs + bh + bc
__device__ float g_epart[4 * M_];          // per-nc partial e sums

// ---------------- helpers ----------------
__device__ __forceinline__ uint32_t smem_u32(const void* p) {
    uint32_t a;
    asm("{ .reg .u64 t; cvta.to.shared.u64 t, %1; cvt.u32.u64 %0, t; }" : "=r"(a) : "l"(p));
    return a;
}
// accurate tanh: 2 MUFU, rel err ~1e-7, saturates correctly
__device__ __forceinline__ float tanh_acc(float x) {
    float e = __expf(2.0f * x);
    return 1.0f - __fdividef(2.0f, e + 1.0f);
}
__device__ __forceinline__ void ldsm4(uint32_t* r, uint32_t addr) {
    asm volatile("ldmatrix.sync.aligned.m8n8.x4.shared.b16 {%0,%1,%2,%3}, [%4];"
                 : "=r"(r[0]), "=r"(r[1]), "=r"(r[2]), "=r"(r[3]) : "r"(addr));
}
__device__ __forceinline__ void mma_f16(float* c, const uint32_t* a, uint32_t b0, uint32_t b1) {
    asm volatile(
        "mma.sync.aligned.m16n8k16.row.col.f32.f16.f16.f32 "
        "{%0,%1,%2,%3},{%4,%5,%6,%7},{%8,%9},{%0,%1,%2,%3};"
        : "+f"(c[0]), "+f"(c[1]), "+f"(c[2]), "+f"(c[3])
        : "r"(a[0]), "r"(a[1]), "r"(a[2]), "r"(a[3]), "r"(b0), "r"(b1));
}
__device__ __forceinline__ void cp16(uint32_t dst, const void* src) {
    asm volatile("cp.async.cg.shared.global [%0], [%1], 16;" :: "r"(dst), "l"(src));
}
__device__ __forceinline__ uint32_t h2u(__half2 h) { return *(uint32_t*)&h; }

// ---------------------------------------------------------------------------
// Merged prologue: apack (blocks 0..16383), bpack (16384..16639),
// dec_comb (16640..17151). All independent writes, one launch.
// ---------------------------------------------------------------------------
__global__ __launch_bounds__(256)
void prologue_kernel(const float* __restrict__ enc,
                     const float* __restrict__ Wh,
                     const float* __restrict__ dec,
                     const float* __restrict__ Ws,
                     const float* __restrict__ bs,
                     const float* __restrict__ bh,
                     const float* __restrict__ bc)
{
    const int bid = blockIdx.x;
    const int tid = threadIdx.x;
    __shared__ float dh[H_];
    __shared__ float red[4][64];

    if (bid < 16384) {
        // ---- apack: enc fp32 -> g_Af fp16; read-once loads, evict-first stores
        const size_t base = (size_t)bid * 1024 + tid * 2;
        #pragma unroll
        for (int j = 0; j < 2; ++j) {
            const size_t i = base + j * 512;
            const float4 v0 = __ldg(((const float4*)enc) + i);
            const float4 v1 = __ldg(((const float4*)enc) + i + 1);
            uint4 o;
            o.x = h2u(__floats2half2_rn(v0.x, v0.y));
            o.y = h2u(__floats2half2_rn(v0.z, v0.w));
            o.z = h2u(__floats2half2_rn(v1.x, v1.y));
            o.w = h2u(__floats2half2_rn(v1.z, v1.w));
            __stcs(((uint4*)g_Af) + (i >> 1), o);
        }
    } else if (bid < 16384 + 256) {
        // ---- bpack: Wh [k][n] -> g_Bf [n][k] fp16 (transpose), 2 n per block ----
        const int n  = (bid - 16384) * 2 + (tid >> 7);
        const int k4 = (tid & 127) * 4;
        __half2 lo = __floats2half2_rn(Wh[(size_t)(k4 + 0) * H_ + n], Wh[(size_t)(k4 + 1) * H_ + n]);
        __half2 hi = __floats2half2_rn(Wh[(size_t)(k4 + 2) * H_ + n], Wh[(size_t)(k4 + 3) * H_ + n]);
        *(uint2*)(g_Bf + (size_t)n * H_ + k4) = make_uint2(h2u(lo), h2u(hi));
    } else {
        // ---- dec_comb: comb[b][n] = dec[b] @ Ws[:,n] + bs + bh + bc ----
        const int id = bid - 16640;        // 0..511
        const int b  = id >> 3;
        const int nh = id & 7;

        dh[tid]       = dec[b * H_ + tid];
        dh[tid + 256] = dec[b * H_ + tid + 256];
        __syncthreads();

        const int nl = tid & 63;
        const int n  = nh * 64 + nl;
        const int ks = tid >> 6;
        float acc = 0.f;
        #pragma unroll 8
        for (int h = ks * 128; h < ks * 128 + 128; ++h)
            acc = fmaf(dh[h], Ws[(size_t)h * H_ + n], acc);
        red[ks][nl] = acc;
        __syncthreads();
        if (ks == 0) {
            float s = red[0][nl] + red[1][nl] + red[2][nl] + red[3][nl];
            g_comb[b * H_ + n] = s + bs[n] + bh[n] + bc[n];
        }
    }
}

// ---------------------------------------------------------------------------
// Main: 128x128x512 fp16 HMMA GEMM + fused tanh/v-dot epilogue
// grid (4 nc, 1024 m-tiles), 256 threads = 8 warps (warpM 0..1 x warpN 0..3)
// warp tile 64x32; k-chunk 64 (128B rows, XOR-swizzled); 3-stage cp.async
// pipeline, fully unrolled; cp.async issues SPREAD across the s-loop.
// ---------------------------------------------------------------------------
#define MAT_BYTES   16384                 // 128 rows x 128B (swizzled, no pad)
#define STAGE_BYTES (2 * MAT_BYTES)       // 32768 (A|B)
#define OFF_COMB  (3 * STAGE_BYTES)       // 98304
#define OFF_WC    (OFF_COMB + 512)
#define OFF_VW    (OFF_WC + 512)
#define OFF_ERED  (OFF_VW + 512)          // 99840: 128 rows x 4 warpN floats
#define SMEM_DYN  (OFF_ERED + 128 * 4 * 4)   // 101888

// swizzled byte offset of (row r, 16B-chunk c) within a 128x128B matrix
#define SWZOFF(r, c) ((uint32_t)((r) * 128 + ((((c) ^ ((r) & 7))) << 4)))

__global__ __launch_bounds__(256, 2)
void attn_hmma_kernel(const float* __restrict__ cov,
                      const float* __restrict__ Wc,
                      const float* __restrict__ v_w)
{
    extern __shared__ char sm[];
    const uint32_t sbase = smem_u32(sm);
    const int tid  = threadIdx.x;
    const int wid  = tid >> 5;
    const int lane = tid & 31;
    const int nc     = blockIdx.x;          // 0..3 (fast-varying: A-tile L2 reuse)
    const int mBase  = blockIdx.y * 128;
    const int ncBase = nc * 128;
    const int b      = mBase >> 11;

    // epilogue constants for this n-chunk (ordered before use by iter-0 sync)
    if (tid < 128) {
        ((float*)(sm + OFF_COMB))[tid] = g_comb[b * H_ + ncBase + tid];
        ((float*)(sm + OFF_WC))[tid]   = Wc[ncBase + tid];
        ((float*)(sm + OFF_VW))[tid]   = v_w[ncBase + tid];
    }

    // cp.async bases: thread covers rows (tid>>3)+32p, 16B-chunk tid&7
    // p in 0..3 per matrix; row step 32 preserves r&7 -> same swizzle term.
    const uint32_t dstA0 = sbase + SWZOFF(tid >> 3, tid & 7);
    const uint32_t dstB0 = dstA0 + MAT_BYTES;
    const char* srcA0 = (const char*)(g_Af + (size_t)(mBase + (tid >> 3)) * H_) + (tid & 7) * 16;
    const char* srcB0 = (const char*)(g_Bf + (size_t)(ncBase + (tid >> 3)) * H_) + (tid & 7) * 16;

// full chunk prefetch (prologue only)
#define CP_CHUNK(kc, stg) do { \
    const uint32_t _so = (uint32_t)(stg) * STAGE_BYTES; \
    const int _ko = (kc) * 128; \
    _Pragma("unroll") \
    for (int _p = 0; _p < 4; ++_p) \
        cp16(dstA0 + _so + _p * 4096, srcA0 + _p * 32768 + _ko); \
    _Pragma("unroll") \
    for (int _p = 0; _p < 4; ++_p) \
        cp16(dstB0 + _so + _p * 4096, srcB0 + _p * 32768 + _ko); \
    asm volatile("cp.async.commit_group;" ::: "memory"); \
} while (0)

// quarter-chunk: one A + one B cp (p = s), issued inside the s-loop
#define CP_PART(kc, stg, p) do { \
    const uint32_t _so = (uint32_t)(stg) * STAGE_BYTES; \
    const int _ko = (kc) * 128; \
    cp16(dstA0 + _so + (p) * 4096, srcA0 + (p) * 32768 + _ko); \
    cp16(dstB0 + _so + (p) * 4096, srcB0 + (p) * 32768 + _ko); \
} while (0)

    const int warpM = wid >> 2;            // 0..1 -> 64 rows
    const int warpN = wid & 3;             // 0..3 -> 32 cols

    // per-s ldsm base offsets; mI/p add a linear 2048B (swizzle term invariant)
    uint32_t offA[4], offB[4];
    {
        const int rowA = warpM * 64 + (lane & 7) + ((lane >> 3) & 1) * 8;
        const int cA   = (lane >> 4);                   // 0..1
        #pragma unroll
        for (int s = 0; s < 4; ++s)
            offA[s] = SWZOFF(rowA, s * 2 + cA);
        const int rowB = warpN * 32 + (lane & 7) + ((lane & 16) ? 8 : 0);
        const int cB   = (lane >> 3) & 1;
        #pragma unroll
        for (int s = 0; s < 4; ++s)
            offB[s] = SWZOFF(rowB, s * 2 + cB);
    }

    float acc[4][4][4];
    #pragma unroll
    for (int i = 0; i < 4; ++i)
        #pragma unroll
        for (int j = 0; j < 4; ++j)
            #pragma unroll
            for (int q = 0; q < 4; ++q) acc[i][j][q] = 0.f;

    // prologue: prefetch chunks 0 and 1 into stages 0 and 1
    CP_CHUNK(0, 0);
    CP_CHUNK(1, 1);

    #pragma unroll
    for (int c = 0; c < 8; ++c) {
        // chunk c guaranteed complete (groups complete in commit order)
        if (c < 7) asm volatile("cp.async.wait_group 1;" ::: "memory");
        else       asm volatile("cp.async.wait_group 0;" ::: "memory");
        __syncthreads();   // single barrier per iteration

        const uint32_t ab = sbase + (c % 3) * STAGE_BYTES;
        const uint32_t bb = ab + MAT_BYTES;

        // fragment rotation: preload s=0; per s run MMA then load s+1 into
        // the same regs (WAR on regs enforces the rotation order)
        uint32_t Af[4][4], Bf[2][4];
        #pragma unroll
        for (int p = 0; p < 2; ++p)    ldsm4(Bf[p], bb + offB[0] + p * 2048);
        #pragma unroll
        for (int mI = 0; mI < 4; ++mI) ldsm4(Af[mI], ab + offA[0] + mI * 2048);

        #pragma unroll
        for (int s = 0; s < 4; ++s) {
            // spread prefetch of chunk c+2: one A + one B cp per s
            if (c + 2 < 8) {
                CP_PART(c + 2, (c + 2) % 3, s);
                if (s == 3) asm volatile("cp.async.commit_group;" ::: "memory");
            }
            #pragma unroll
            for (int mI = 0; mI < 4; ++mI)
                #pragma unroll
                for (int nI = 0; nI < 4; ++nI)
                    mma_f16(acc[mI][nI], Af[mI], Bf[nI >> 1][(nI & 1) * 2], Bf[nI >> 1][(nI & 1) * 2 + 1]);
            if (s < 3) {
                #pragma unroll
                for (int p = 0; p < 2; ++p)    ldsm4(Bf[p], bb + offB[s + 1] + p * 2048);
                #pragma unroll
                for (int mI = 0; mI < 4; ++mI) ldsm4(Af[mI], ab + offA[s + 1] + mI * 2048);
            }
        }
    }
#undef CP_CHUNK
#undef CP_PART

    // ---- fused epilogue: tanh + v-dot; shuffle-reduce the 4 col-threads,
    //      then smem-reduce the 4 warpN warps ----
    const float* sComb = (const float*)(sm + OFF_COMB);
    const float* sWc   = (const float*)(sm + OFF_WC);
    const float* sVw   = (const float*)(sm + OFF_VW);
    float* ered = (float*)(sm + OFF_ERED);    // [128 rows][4 warpN]

    #pragma unroll
    for (int mI = 0; mI < 4; ++mI) {
        const int mlo = warpM * 64 + mI * 16 + (lane >> 2);
        const float covlo = cov[mBase + mlo];
        const float covhi = cov[mBase + mlo + 8];
        float elo = 0.f, ehi = 0.f;
        #pragma unroll
        for (int nI = 0; nI < 4; ++nI) {
            #pragma unroll
            for (int t = 0; t < 2; ++t) {
                const int n = warpN * 32 + nI * 8 + (lane & 3) * 2 + t;
                const float cb = sComb[n], wc = sWc[n], vw = sVw[n];
                elo = fmaf(vw, tanh_acc(acc[mI][nI][t]     + cb + covlo * wc), elo);
                ehi = fmaf(vw, tanh_acc(acc[mI][nI][t + 2] + cb + covhi * wc), ehi);
            }
        }
        // reduce over lane&3 (the 4 column threads of each row)
        elo += __shfl_xor_sync(0xFFFFFFFFu, elo, 1);
        elo += __shfl_xor_sync(0xFFFFFFFFu, elo, 2);
        ehi += __shfl_xor_sync(0xFFFFFFFFu, ehi, 1);
        ehi += __shfl_xor_sync(0xFFFFFFFFu, ehi, 2);
        if ((lane & 3) == 0) {
            ered[mlo * 4 + warpN]       = elo;
            ered[(mlo + 8) * 4 + warpN] = ehi;
        }
    }
    __syncthreads();
    if (tid < 128) {
        const float s = ered[tid * 4] + ered[tid * 4 + 1] + ered[tid * 4 + 2] + ered[tid * 4 + 3];
        g_epart[nc * M_ + mBase + tid] = s;
    }
}

// ---------------------------------------------------------------------------
// Softmax over S=2048 per batch + coverage update (v_b shift-invariant)
// ---------------------------------------------------------------------------
__global__ __launch_bounds__(256)
void softmax_kernel(const float* __restrict__ cov, float* __restrict__ out)
{
    const int b   = blockIdx.x;
    const int tid = threadIdx.x;
    __shared__ float red[256];

    float local[8];
    float mx = -INFINITY;
    #pragma unroll
    for (int i = 0; i < 8; ++i) {
        const int idx = b * S_ + tid + i * 256;
        local[i] = g_epart[idx] + g_epart[M_ + idx] + g_epart[2 * M_ + idx] + g_epart[3 * M_ + idx];
        mx = fmaxf(mx, local[i]);
    }
    red[tid] = mx;
    __syncthreads();
    for (int s = 128; s > 0; s >>= 1) {
        if (tid < s) red[tid] = fmaxf(red[tid], red[tid + s]);
        __syncthreads();
    }
    const float m = red[0];
    __syncthreads();

    float sum = 0.f;
    #pragma unroll
    for (int i = 0; i < 8; ++i) {
        local[i] = __expf(local[i] - m);
        sum += local[i];
    }
    red[tid] = sum;
    __syncthreads();
    for (int s = 128; s > 0; s >>= 1) {
        if (tid < s) red[tid] += red[tid + s];
        __syncthreads();
    }
    const float inv = 1.0f / red[0];

    #pragma unroll
    for (int i = 0; i < 8; ++i) {
        const int idx = b * S_ + tid + i * 256;
        const float a = local[i] * inv;
        out[idx]      = a;
        out[M_ + idx] = cov[idx] + a;
    }
}

// ---------------------------------------------------------------------------
extern "C" void kernel_launch(void* const* d_in, const int* in_sizes, int n_in,
                              void* d_out, int out_size)
{
    const float* enc = (const float*)d_in[0];
    const float* dec = (const float*)d_in[1];
    const float* cov = (const float*)d_in[2];
    const float* Wh  = (const float*)d_in[3];
    const float* bh  = (const float*)d_in[4];
    const float* Ws  = (const float*)d_in[5];
    const float* bs  = (const float*)d_in[6];
    const float* Wc  = (const float*)d_in[7];
    const float* bc  = (const float*)d_in[8];
    const float* v_w = (const float*)d_in[9];
    float* out = (float*)d_out;

    cudaFuncSetAttribute(attn_hmma_kernel,
                         cudaFuncAttributeMaxDynamicSharedMemorySize, SMEM_DYN);

    prologue_kernel<<<17152, 256>>>(enc, Wh, dec, Ws, bs, bh, bc);
    attn_hmma_kernel<<<dim3(4, M_ / 128), 256, SMEM_DYN>>>(cov, Wc, v_w);
    softmax_kernel<<<B_, 256>>>(cov, out);
}